// round 6
// baseline (speedup 1.0000x reference)
#include <cuda_runtime.h>
#include <math.h>

// ---------------- problem constants ----------------
constexpr int NSRC  = 10000;
constexpr int NEDGE = 320000;
constexpr int DIM   = 128;
constexpr int EDIM  = 236;
constexpr int TOPN  = 6;
constexpr float BN_EPS = 1e-5f;

// ---------------- static device scratch ----------------
__device__ float d_agg[NSRC * EDIM];            // segment-summed relu(path_feats)
__device__ float d_h[3 * NSRC * DIM];           // h_i = srcs + agg@We_i + be_i
__device__ float d_t[3 * NSRC * DIM];           // t_i = h_i@W1_i  (bn-relu applied in place)
__device__ float d_hcat[NSRC * 3 * DIM];        // concat(hs)
__device__ float d_tmp[NSRC * DIM];             // lin1 output
__device__ float d_nodeproj[NSRC * DIM];        // node_emb@pe_src_W + (pe_src_b+pe_tgt_b)
__device__ float d_hpath[(size_t)NEDGE * DIM];  // big GEMM output (pre-BN)
__device__ float d_scores[NEDGE];
__device__ float d_stats[1024];                 // 4 groups x (sum[128], sumsq[128])
__device__ float d_bns[512];                    // bn scale per group
__device__ float d_bnsh[512];                   // bn shift per group
__device__ float d_pebias[DIM];
__device__ int   d_cnt[NSRC];
__device__ int   d_off[NSRC + 1];
__device__ int   d_cursor[NSRC];
__device__ int   d_elist[NEDGE];
__device__ float d_cv[256 * TOPN];
__device__ int   d_ci[256 * TOPN];

// ---------------- packed f32x2 FMA (full-rate fp32 on sm_103a) ----------------
union F2LL { float2 f2; unsigned long long ll; };
__device__ __forceinline__ float2 ffma2(float2 a, float2 b, float2 c) {
    F2LL ua, ub, uc, ud;
    ua.f2 = a; ub.f2 = b; uc.f2 = c;
    asm("fma.rn.f32x2 %0, %1, %2, %3;"
        : "=l"(ud.ll) : "l"(ua.ll), "l"(ub.ll), "l"(uc.ll));
    return ud.f2;
}

// ---------------- CSR build ----------------
__global__ void k_zero(int* cnt, float* stats) {
    int i = blockIdx.x * blockDim.x + threadIdx.x;
    if (i < NSRC) cnt[i] = 0;
    if (i < 1024) stats[i] = 0.f;
}

__global__ void k_hist(const int* __restrict__ src, int* cnt) {
    int i = blockIdx.x * blockDim.x + threadIdx.x;
    if (i < NEDGE) atomicAdd(&cnt[src[i]], 1);
}

__global__ void k_scan(const int* __restrict__ cnt, int* off, int* cursor) {
    __shared__ int warp_sums[32];
    __shared__ int s_carry;
    if (threadIdx.x == 0) s_carry = 0;
    __syncthreads();
    const int lane = threadIdx.x & 31, wid = threadIdx.x >> 5;
    for (int base = 0; base < NSRC; base += blockDim.x) {
        int i = base + threadIdx.x;
        int v = (i < NSRC) ? cnt[i] : 0;
        int x = v;
        #pragma unroll
        for (int d = 1; d < 32; d <<= 1) {
            int y = __shfl_up_sync(~0u, x, d);
            if (lane >= d) x += y;
        }
        if (lane == 31) warp_sums[wid] = x;
        __syncthreads();
        if (wid == 0) {
            int w = warp_sums[lane];
            #pragma unroll
            for (int d = 1; d < 32; d <<= 1) {
                int y = __shfl_up_sync(~0u, w, d);
                if (lane >= d) w += y;
            }
            warp_sums[lane] = w;
        }
        __syncthreads();
        int warp_off = (wid == 0) ? 0 : warp_sums[wid - 1];
        int excl = s_carry + warp_off + x - v;
        if (i < NSRC) { off[i] = excl; cursor[i] = excl; }
        __syncthreads();
        if (threadIdx.x == blockDim.x - 1) s_carry += warp_off + x;
        __syncthreads();
    }
    if (threadIdx.x == 0) off[NSRC] = s_carry;
}

__global__ void k_scatter(const int* __restrict__ src, int* cursor, int* elist) {
    int e = blockIdx.x * blockDim.x + threadIdx.x;
    if (e < NEDGE) {
        int p = atomicAdd(&cursor[src[e]], 1);
        elist[p] = e;
    }
}

// segment-sum of relu(path_feats), one block per source node, coalesced, no float atomics
__global__ void k_agg(const float* __restrict__ pf, const int* __restrict__ elist,
                      const int* __restrict__ off, float* __restrict__ agg) {
    int s = blockIdx.x;
    int d = threadIdx.x;
    int beg = off[s], end = off[s + 1];
    float acc = 0.f;
    int p = beg;
    for (; p + 1 < end; p += 2) {
        int e0 = __ldg(&elist[p]), e1 = __ldg(&elist[p + 1]);
        if (d < EDIM) {
            float v0 = __ldg(&pf[(size_t)e0 * EDIM + d]);
            float v1 = __ldg(&pf[(size_t)e1 * EDIM + d]);
            acc += fmaxf(v0, 0.f) + fmaxf(v1, 0.f);
        }
    }
    if (p < end) {
        int e = __ldg(&elist[p]);
        if (d < EDIM) acc += fmaxf(__ldg(&pf[(size_t)e * EDIM + d]), 0.f);
    }
    if (d < EDIM) agg[s * EDIM + d] = acc;
}

// ---------------- generic N=128 GEMM (f32x2 inner loop, fused epilogues) ----------------
// C[M,128] = A[M,K] @ W[K,128]  (+bias) (+residual direct/gather) (+relu) (+column stats)
template <int K, bool BIAS, bool RELU, int RESMODE /*0 none,1 direct,2 gather*/, bool STATS>
__global__ void __launch_bounds__(256) k_gemm(
    const float* __restrict__ A, int aBatch,
    const float* __restrict__ W, int wBatch,
    const float* __restrict__ bias, int biasBatch,
    const float* __restrict__ res, const int* __restrict__ gidx,
    float* __restrict__ C, int cBatch, int cRowStride,
    float* __restrict__ stats, int statsBatch, int M)
{
    extern __shared__ float smem[];
    float* Ws = smem;                 // K * 128
    float* As = smem + K * 128;       // 8 * 128
    float* sred = As + 1024;          // 2*2048 if STATS

    const int tid = threadIdx.x;
    const int tx = tid & 15, ty = tid >> 4;
    const int z = blockIdx.z;
    const float* Ab = A + (size_t)z * aBatch;
    const float* Wb = W + (size_t)z * wBatch;
    float* Cb = C + (size_t)z * cBatch;

    for (int i = tid; i < K * 32; i += 256)
        ((float4*)Ws)[i] = ((const float4*)Wb)[i];

    float2 acc[8][4];
    #pragma unroll
    for (int i = 0; i < 8; i++)
        #pragma unroll
        for (int j = 0; j < 4; j++) acc[i][j] = make_float2(0.f, 0.f);

    const int row0 = blockIdx.x * 128;
    const int ar = tid >> 1, ac4 = (tid & 1) * 4;
    const int garow = row0 + ar;
    const float* aptr = (garow < M) ? (Ab + (size_t)garow * K) : nullptr;

    for (int k0 = 0; k0 < K; k0 += 8) {
        float4 av = make_float4(0.f, 0.f, 0.f, 0.f);
        if (aptr != nullptr && (k0 + ac4) < K)
            av = *(const float4*)(aptr + k0 + ac4);
        __syncthreads();   // prior compute done (first iter: Ws loaded)
        As[(ac4 + 0) * 128 + ar] = av.x;
        As[(ac4 + 1) * 128 + ar] = av.y;
        As[(ac4 + 2) * 128 + ar] = av.z;
        As[(ac4 + 3) * 128 + ar] = av.w;
        __syncthreads();
        #pragma unroll
        for (int kk = 0; kk < 8; kk++) {
            if (k0 + kk < K) {
                float4 a0 = *(const float4*)&As[kk * 128 + ty * 8];
                float4 a1 = *(const float4*)&As[kk * 128 + ty * 8 + 4];
                float4 b0 = *(const float4*)&Ws[(k0 + kk) * 128 + tx * 8];
                float4 b1 = *(const float4*)&Ws[(k0 + kk) * 128 + tx * 8 + 4];
                float aa[8] = {a0.x, a0.y, a0.z, a0.w, a1.x, a1.y, a1.z, a1.w};
                float2 bb[4] = {{b0.x, b0.y}, {b0.z, b0.w}, {b1.x, b1.y}, {b1.z, b1.w}};
                #pragma unroll
                for (int i = 0; i < 8; i++) {
                    float2 ai2 = make_float2(aa[i], aa[i]);
                    #pragma unroll
                    for (int j = 0; j < 4; j++)
                        acc[i][j] = ffma2(ai2, bb[j], acc[i][j]);
                }
            }
        }
    }

    // epilogue
    float colsum[8], colsq[8];
    if (STATS) {
        #pragma unroll
        for (int j = 0; j < 8; j++) { colsum[j] = 0.f; colsq[j] = 0.f; }
    }
    float bv[8];
    if (BIAS) {
        const float* bb = bias + (size_t)z * biasBatch + tx * 8;
        #pragma unroll
        for (int j = 0; j < 8; j++) bv[j] = bb[j];
    }
    #pragma unroll
    for (int i = 0; i < 8; i++) {
        int r = row0 + ty * 8 + i;
        if (r < M) {
            float vals[8];
            #pragma unroll
            for (int j = 0; j < 4; j++) { vals[2*j] = acc[i][j].x; vals[2*j+1] = acc[i][j].y; }
            if (BIAS) {
                #pragma unroll
                for (int j = 0; j < 8; j++) vals[j] += bv[j];
            }
            if (RESMODE != 0) {
                const float* rp;
                if (RESMODE == 1) rp = res + (size_t)r * DIM + tx * 8;
                else { int g = __ldg(&gidx[r]); rp = res + (size_t)g * DIM + tx * 8; }
                float4 r0 = *(const float4*)rp;
                float4 r1 = *(const float4*)(rp + 4);
                vals[0]+=r0.x; vals[1]+=r0.y; vals[2]+=r0.z; vals[3]+=r0.w;
                vals[4]+=r1.x; vals[5]+=r1.y; vals[6]+=r1.z; vals[7]+=r1.w;
            }
            if (RELU) {
                #pragma unroll
                for (int j = 0; j < 8; j++) vals[j] = fmaxf(vals[j], 0.f);
            }
            float* cp = Cb + (size_t)r * cRowStride + tx * 8;
            *(float4*)cp       = make_float4(vals[0], vals[1], vals[2], vals[3]);
            *(float4*)(cp + 4) = make_float4(vals[4], vals[5], vals[6], vals[7]);
            if (STATS) {
                #pragma unroll
                for (int j = 0; j < 8; j++) { colsum[j] += vals[j]; colsq[j] += vals[j] * vals[j]; }
            }
        }
    }
    if (STATS) {
        __syncthreads();
        #pragma unroll
        for (int j = 0; j < 8; j++) {
            sred[ty * 128 + tx * 8 + j] = colsum[j];
            sred[2048 + ty * 128 + tx * 8 + j] = colsq[j];
        }
        __syncthreads();
        if (tid < 128) {
            float s = 0.f, q = 0.f;
            #pragma unroll
            for (int w = 0; w < 16; w++) {
                s += sred[w * 128 + tid];
                q += sred[2048 + w * 128 + tid];
            }
            float* st = stats + (size_t)z * statsBatch;
            atomicAdd(&st[tid], s);
            atomicAdd(&st[128 + tid], q);
        }
    }
}

// ---------------- BN finalize / apply ----------------
__global__ void k_bnfin(const float* __restrict__ stats, const float* __restrict__ gamma,
                        const float* __restrict__ beta, float invM,
                        float* scale, float* shift, int G) {
    int i = blockIdx.x * blockDim.x + threadIdx.x;
    if (i >= G * 128) return;
    int g = i / 128, c = i % 128;
    float mean = stats[g * 256 + c] * invM;
    float ex2  = stats[g * 256 + 128 + c] * invM;
    float var = ex2 - mean * mean;
    float s = gamma[i] * rsqrtf(var + BN_EPS);
    scale[i] = s;
    shift[i] = beta[i] - mean * s;
}

__global__ void k_bnrelu(float* t, const float* __restrict__ scale, const float* __restrict__ shift) {
    int i = blockIdx.x * blockDim.x + threadIdx.x;   // over 3*NSRC*32 float4
    const int total = 3 * NSRC * (DIM / 4);
    if (i >= total) return;
    int c4 = i & 31;
    int z = i / (NSRC * 32);
    float4 v = ((float4*)t)[i];
    float4 sc = ((const float4*)scale)[z * 32 + c4];
    float4 sh = ((const float4*)shift)[z * 32 + c4];
    v.x = fmaxf(v.x * sc.x + sh.x, 0.f);
    v.y = fmaxf(v.y * sc.y + sh.y, 0.f);
    v.z = fmaxf(v.z * sc.z + sh.z, 0.f);
    v.w = fmaxf(v.w * sc.w + sh.w, 0.f);
    ((float4*)t)[i] = v;
}

__global__ void k_pebias(const float* a, const float* b, float* o) {
    int i = threadIdx.x;
    if (i < DIM) o[i] = a[i] + b[i];
}

// ---------------- score (BN+relu+dot fused) ----------------
__global__ void k_score(const float* __restrict__ hpath, const float* __restrict__ scale,
                        const float* __restrict__ shift, const float* __restrict__ sw,
                        float* __restrict__ scores) {
    int gt = blockIdx.x * blockDim.x + threadIdx.x;
    int e = gt >> 5, lane = gt & 31;
    if (e >= NEDGE) return;
    float4 h = ((const float4*)(hpath + (size_t)e * DIM))[lane];
    float4 sc = __ldg(&((const float4*)scale)[lane]);
    float4 sh = __ldg(&((const float4*)shift)[lane]);
    float4 w  = __ldg(&((const float4*)sw)[lane]);
    float s = fmaxf(h.x * sc.x + sh.x, 0.f) * w.x
            + fmaxf(h.y * sc.y + sh.y, 0.f) * w.y
            + fmaxf(h.z * sc.z + sh.z, 0.f) * w.z
            + fmaxf(h.w * sc.w + sh.w, 0.f) * w.w;
    #pragma unroll
    for (int o = 16; o > 0; o >>= 1) s += __shfl_xor_sync(~0u, s, o);
    if (lane == 0) scores[e] = s;
}

// ---------------- top-k (exact JAX tie-break: value desc, index asc) ----------------
__device__ __forceinline__ bool kbetter(float a, int ia, float b, int ib) {
    return (a > b) || (a == b && ia < ib);
}

__device__ __forceinline__ void kmerge(const float* av, const int* ai,
                                       const float* bv, const int* bi,
                                       float* ov, int* oi) {
    int x = 0, y = 0;
    for (int k = 0; k < TOPN; k++) {
        if (kbetter(av[x], ai[x], bv[y], bi[y])) { ov[k] = av[x]; oi[k] = ai[x]; x++; }
        else                                      { ov[k] = bv[y]; oi[k] = bi[y]; y++; }
    }
}

__device__ __forceinline__ void block_topk_reduce(float* v, int* id, float* sv, int* si,
                                                  int t) {
    for (int k = 0; k < TOPN; k++) { sv[t * TOPN + k] = v[k]; si[t * TOPN + k] = id[k]; }
    __syncthreads();
    for (int strd = 128; strd > 0; strd >>= 1) {
        if (t < strd) {
            float av[TOPN], bv[TOPN], ov[TOPN];
            int ai[TOPN], bi[TOPN], oi[TOPN];
            for (int k = 0; k < TOPN; k++) {
                av[k] = sv[t * TOPN + k];            ai[k] = si[t * TOPN + k];
                bv[k] = sv[(t + strd) * TOPN + k];   bi[k] = si[(t + strd) * TOPN + k];
            }
            kmerge(av, ai, bv, bi, ov, oi);
            for (int k = 0; k < TOPN; k++) { sv[t * TOPN + k] = ov[k]; si[t * TOPN + k] = oi[k]; }
        }
        __syncthreads();
    }
}

__global__ void k_top1(const float* __restrict__ scores, float* cv, int* ci) {
    __shared__ float sv[256 * TOPN];
    __shared__ int   si[256 * TOPN];
    const float NEG = __int_as_float(0xff800000);  // -inf
    float v[TOPN]; int id[TOPN];
    for (int k = 0; k < TOPN; k++) { v[k] = NEG; id[k] = 0x7fffffff; }
    int stride = gridDim.x * blockDim.x;
    for (int i = blockIdx.x * blockDim.x + threadIdx.x; i < NEDGE; i += stride) {
        float s = scores[i];
        if (kbetter(s, i, v[TOPN - 1], id[TOPN - 1])) {
            int p = TOPN - 1;
            while (p > 0 && kbetter(s, i, v[p - 1], id[p - 1])) {
                v[p] = v[p - 1]; id[p] = id[p - 1]; p--;
            }
            v[p] = s; id[p] = i;
        }
    }
    block_topk_reduce(v, id, sv, si, threadIdx.x);
    if (threadIdx.x == 0)
        for (int k = 0; k < TOPN; k++) {
            cv[blockIdx.x * TOPN + k] = sv[k];
            ci[blockIdx.x * TOPN + k] = si[k];
        }
}

__global__ void k_top2(const float* __restrict__ cv, const int* __restrict__ ci, float* out) {
    __shared__ float sv[256 * TOPN];
    __shared__ int   si[256 * TOPN];
    int t = threadIdx.x;
    float v[TOPN]; int id[TOPN];
    for (int k = 0; k < TOPN; k++) { v[k] = cv[t * TOPN + k]; id[k] = ci[t * TOPN + k]; }
    block_topk_reduce(v, id, sv, si, t);
    if (t == 0)
        for (int k = 0; k < TOPN; k++) {
            out[k]        = sv[k];
            out[TOPN + k] = (float)si[k];
        }
}

// ---------------- launch ----------------
extern "C" void kernel_launch(void* const* d_in, const int* in_sizes, int n_in,
                              void* d_out, int out_size) {
    const float* F[20];
    for (int i = 0; i < 20 && i < n_in; i++) F[i] = (const float*)d_in[i];

    const float *paths_srcs, *path_feats, *conv_edge_W, *conv_edge_b, *conv_W1,
                *conv_bn_g, *conv_bn_b, *conv_W2, *lin1_W, *lin1_b, *lin2_W, *lin2_b,
                *pe_src_W, *pe_src_b, *pe_tgt_W, *pe_tgt_b, *pe_bn_g, *pe_bn_b, *score_w;
    const int* src_ids;

    if (in_sizes[2] == NEDGE) {  // setup_inputs dict order (src_ids third)
        paths_srcs = F[0]; path_feats = F[1]; src_ids = (const int*)d_in[2];
        conv_edge_W = F[3]; conv_edge_b = F[4]; conv_W1 = F[5];
        conv_bn_g = F[6]; conv_bn_b = F[7]; conv_W2 = F[8];
        lin1_W = F[9]; lin1_b = F[10]; lin2_W = F[11]; lin2_b = F[12];
        pe_src_W = F[13]; pe_src_b = F[14]; pe_tgt_W = F[15]; pe_tgt_b = F[16];
        pe_bn_g = F[17]; pe_bn_b = F[18]; score_w = F[19];
    } else {                     // reference() signature order (src_ids last)
        paths_srcs = F[0]; path_feats = F[1];
        conv_edge_W = F[2]; conv_edge_b = F[3]; conv_W1 = F[4];
        conv_bn_g = F[5]; conv_bn_b = F[6]; conv_W2 = F[7];
        lin1_W = F[8]; lin1_b = F[9]; lin2_W = F[10]; lin2_b = F[11];
        pe_src_W = F[12]; pe_src_b = F[13]; pe_tgt_W = F[14]; pe_tgt_b = F[15];
        pe_bn_g = F[16]; pe_bn_b = F[17]; score_w = F[18];
        src_ids = (const int*)d_in[19];
    }

    auto sym = [](const void* s) { void* p = nullptr; cudaGetSymbolAddress(&p, s); return p; };
    float* agg      = (float*)sym(d_agg);
    float* h        = (float*)sym(d_h);
    float* t        = (float*)sym(d_t);
    float* hcat     = (float*)sym(d_hcat);
    float* tmp      = (float*)sym(d_tmp);
    float* nodeproj = (float*)sym(d_nodeproj);
    float* hpath    = (float*)sym(d_hpath);
    float* scores   = (float*)sym(d_scores);
    float* stats    = (float*)sym(d_stats);
    float* bns      = (float*)sym(d_bns);
    float* bnsh     = (float*)sym(d_bnsh);
    float* pebias   = (float*)sym(d_pebias);
    int*   cnt      = (int*)sym(d_cnt);
    int*   off      = (int*)sym(d_off);
    int*   cursor   = (int*)sym(d_cursor);
    int*   elist    = (int*)sym(d_elist);
    float* cv       = (float*)sym(d_cv);
    int*   ci       = (int*)sym(d_ci);
    float* out      = (float*)d_out;

    const dim3 blk(256);
    const int NODE_BLKS = (NSRC + 127) / 128;    // 79
    const int EDGE_BLKS = NEDGE / 128;           // 2500

    // dynamic smem sizes (floats): W panel + A tile (+stats reduce)
    const size_t sm236   = (size_t)(236 * 128 + 1024) * 4;
    const size_t sm236s  = (size_t)(236 * 128 + 1024 + 4096) * 4;
    const size_t sm128   = (size_t)(128 * 128 + 1024) * 4;
    const size_t sm128s  = (size_t)(128 * 128 + 1024 + 4096) * 4;
    const size_t sm384   = (size_t)(384 * 128 + 1024) * 4;

    cudaFuncSetAttribute(k_gemm<236, true,  false, 1, false>, cudaFuncAttributeMaxDynamicSharedMemorySize, (int)sm236);
    cudaFuncSetAttribute(k_gemm<128, false, false, 0, true >, cudaFuncAttributeMaxDynamicSharedMemorySize, (int)sm128s);
    cudaFuncSetAttribute(k_gemm<128, false, false, 0, false>, cudaFuncAttributeMaxDynamicSharedMemorySize, (int)sm128);
    cudaFuncSetAttribute(k_gemm<384, true,  true,  0, false>, cudaFuncAttributeMaxDynamicSharedMemorySize, (int)sm384);
    cudaFuncSetAttribute(k_gemm<128, true,  false, 0, false>, cudaFuncAttributeMaxDynamicSharedMemorySize, (int)sm128);
    cudaFuncSetAttribute(k_gemm<236, false, false, 2, true >, cudaFuncAttributeMaxDynamicSharedMemorySize, (int)sm236s);

    // 1) CSR build + segment sum of relu(path_feats)
    k_zero<<<(NSRC + 255) / 256, blk>>>(cnt, stats);
    k_hist<<<(NEDGE + 255) / 256, blk>>>(src_ids, cnt);
    k_scan<<<1, 1024>>>(cnt, off, cursor);
    k_scatter<<<(NEDGE + 255) / 256, blk>>>(src_ids, cursor, elist);
    k_agg<<<NSRC, blk>>>(path_feats, elist, off, agg);

    // 2) h_i = agg @ We_i + be_i + paths_srcs   (batched over i)
    k_gemm<236, true, false, 1, false><<<dim3(NODE_BLKS, 1, 3), blk, sm236>>>(
        agg, 0, conv_edge_W, 236 * 128, conv_edge_b, 128,
        paths_srcs, nullptr, h, NSRC * DIM, DIM, nullptr, 0, NSRC);

    // 3) t_i = h_i @ W1_i  with fused BN stats
    k_gemm<128, false, false, 0, true><<<dim3(NODE_BLKS, 1, 3), blk, sm128s>>>(
        h, NSRC * DIM, conv_W1, DIM * DIM, nullptr, 0,
        nullptr, nullptr, t, NSRC * DIM, DIM, stats, 256, NSRC);

    // 4) BN finalize (3 conv groups) + apply BN+relu in place
    k_bnfin<<<2, blk>>>(stats, conv_bn_g, conv_bn_b, 1.f / NSRC, bns, bnsh, 3);
    k_bnrelu<<<(3 * NSRC * 32 + 255) / 256, blk>>>(t, bns, bnsh);

    // 5) hs_i = z_i @ W2_i  -> write into hcat columns [i*128, i*128+128)
    k_gemm<128, false, false, 0, false><<<dim3(NODE_BLKS, 1, 3), blk, sm128>>>(
        t, NSRC * DIM, conv_W2, DIM * DIM, nullptr, 0,
        nullptr, nullptr, hcat, 128, 3 * DIM, nullptr, 0, NSRC);

    // 6) lin1 (relu) and lin2 -> node_emb directly into d_out
    k_gemm<384, true, true, 0, false><<<dim3(NODE_BLKS, 1, 1), blk, sm384>>>(
        hcat, 0, lin1_W, 0, lin1_b, 0, nullptr, nullptr, tmp, 0, DIM, nullptr, 0, NSRC);
    k_gemm<128, true, false, 0, false><<<dim3(NODE_BLKS, 1, 1), blk, sm128>>>(
        tmp, 0, lin2_W, 0, lin2_b, 0, nullptr, nullptr, out, 0, DIM, nullptr, 0, NSRC);

    // 7) node_proj = node_emb @ pe_src_W + (pe_src_b + pe_tgt_b)
    k_pebias<<<1, 128>>>(pe_src_b, pe_tgt_b, pebias);
    k_gemm<128, true, false, 0, false><<<dim3(NODE_BLKS, 1, 1), blk, sm128>>>(
        out, 0, pe_src_W, 0, pebias, 0, nullptr, nullptr, nodeproj, 0, DIM, nullptr, 0, NSRC);

    // 8) hpath = path_feats @ pe_tgt_W + node_proj[src]   (fused gather + BN stats)
    k_gemm<236, false, false, 2, true><<<dim3(EDGE_BLKS, 1, 1), blk, sm236s>>>(
        path_feats, 0, pe_tgt_W, 0, nullptr, 0,
        nodeproj, src_ids, hpath, 0, DIM, stats + 768, 0, NEDGE);

    // 9) pe BN finalize, fused BN+relu+dot(score_w)
    k_bnfin<<<1, 128>>>(stats + 768, pe_bn_g, pe_bn_b, 1.f / NEDGE, bns + 384, bnsh + 384, 1);
    k_score<<<(NEDGE * 32 + 255) / 256, blk>>>(hpath, bns + 384, bnsh + 384, score_w, scores);

    // 10) top-6 (two-stage block merge), write tail of d_out
    k_top1<<<256, blk>>>(scores, cv, ci);
    k_top2<<<1, blk>>>(cv, ci, out + (size_t)NSRC * DIM);
}

// round 7
// speedup vs baseline: 1.6711x; 1.6711x over previous
#include <cuda_runtime.h>
#include <math.h>

// ---------------- problem constants ----------------
constexpr int NSRC  = 10000;
constexpr int NEDGE = 320000;
constexpr int DIM   = 128;
constexpr int EDIM  = 236;
constexpr int TOPN  = 6;
constexpr float BN_EPS = 1e-5f;

// ---------------- static device scratch ----------------
__device__ float d_agg[NSRC * EDIM];
__device__ float d_h[3 * NSRC * DIM];
__device__ float d_t[3 * NSRC * DIM];
__device__ float d_hcat[NSRC * 3 * DIM];
__device__ float d_tmp[NSRC * DIM];
__device__ float d_nodeproj[NSRC * DIM];
__device__ float d_hpath[(size_t)NEDGE * DIM];
__device__ float d_scores[NEDGE];
__device__ float d_stats[1024];
__device__ float d_bns[512];
__device__ float d_bnsh[512];
__device__ float d_pebias[DIM];
__device__ int   d_cnt[NSRC];
__device__ int   d_off[NSRC + 1];
__device__ int   d_cursor[NSRC];
__device__ int   d_elist[NEDGE];
__device__ float d_cv[256 * TOPN];
__device__ int   d_ci[256 * TOPN];

// ---------------- packed f32x2 FMA ----------------
union F2LL { float2 f2; unsigned long long ll; };
__device__ __forceinline__ float2 ffma2(float2 a, float2 b, float2 c) {
    F2LL ua, ub, uc, ud;
    ua.f2 = a; ub.f2 = b; uc.f2 = c;
    asm("fma.rn.f32x2 %0, %1, %2, %3;"
        : "=l"(ud.ll) : "l"(ua.ll), "l"(ub.ll), "l"(uc.ll));
    return ud.f2;
}

// ---------------- CSR build ----------------
__global__ void k_zero(int* cnt, float* stats) {
    int i = blockIdx.x * blockDim.x + threadIdx.x;
    if (i < NSRC) cnt[i] = 0;
    if (i < 1024) stats[i] = 0.f;
}

__global__ void k_hist(const int* __restrict__ src, int* cnt) {
    int i = blockIdx.x * blockDim.x + threadIdx.x;
    if (i < NEDGE) atomicAdd(&cnt[src[i]], 1);
}

__global__ void k_scan(const int* __restrict__ cnt, int* off, int* cursor) {
    __shared__ int warp_sums[32];
    __shared__ int s_carry;
    if (threadIdx.x == 0) s_carry = 0;
    __syncthreads();
    const int lane = threadIdx.x & 31, wid = threadIdx.x >> 5;
    for (int base = 0; base < NSRC; base += blockDim.x) {
        int i = base + threadIdx.x;
        int v = (i < NSRC) ? cnt[i] : 0;
        int x = v;
        #pragma unroll
        for (int d = 1; d < 32; d <<= 1) {
            int y = __shfl_up_sync(~0u, x, d);
            if (lane >= d) x += y;
        }
        if (lane == 31) warp_sums[wid] = x;
        __syncthreads();
        if (wid == 0) {
            int w = warp_sums[lane];
            #pragma unroll
            for (int d = 1; d < 32; d <<= 1) {
                int y = __shfl_up_sync(~0u, w, d);
                if (lane >= d) w += y;
            }
            warp_sums[lane] = w;
        }
        __syncthreads();
        int warp_off = (wid == 0) ? 0 : warp_sums[wid - 1];
        int excl = s_carry + warp_off + x - v;
        if (i < NSRC) { off[i] = excl; cursor[i] = excl; }
        __syncthreads();
        if (threadIdx.x == blockDim.x - 1) s_carry += warp_off + x;
        __syncthreads();
    }
    if (threadIdx.x == 0) off[NSRC] = s_carry;
}

__global__ void k_scatter(const int* __restrict__ src, int* cursor, int* elist) {
    int e = blockIdx.x * blockDim.x + threadIdx.x;
    if (e < NEDGE) {
        int p = atomicAdd(&cursor[src[e]], 1);
        elist[p] = e;
    }
}

// segment-sum of relu(path_feats): one block per source, coalesced, no float atomics
__global__ void k_agg(const float* __restrict__ pf, const int* __restrict__ elist,
                      const int* __restrict__ off, float* __restrict__ agg) {
    int s = blockIdx.x;
    int d = threadIdx.x;
    int beg = off[s], end = off[s + 1];
    float acc = 0.f;
    int p = beg;
    for (; p + 3 < end; p += 4) {
        int e0 = __ldg(&elist[p]),     e1 = __ldg(&elist[p + 1]);
        int e2 = __ldg(&elist[p + 2]), e3 = __ldg(&elist[p + 3]);
        if (d < EDIM) {
            float v0 = __ldg(&pf[(size_t)e0 * EDIM + d]);
            float v1 = __ldg(&pf[(size_t)e1 * EDIM + d]);
            float v2 = __ldg(&pf[(size_t)e2 * EDIM + d]);
            float v3 = __ldg(&pf[(size_t)e3 * EDIM + d]);
            acc += fmaxf(v0, 0.f) + fmaxf(v1, 0.f) + fmaxf(v2, 0.f) + fmaxf(v3, 0.f);
        }
    }
    for (; p < end; p++) {
        int e = __ldg(&elist[p]);
        if (d < EDIM) acc += fmaxf(__ldg(&pf[(size_t)e * EDIM + d]), 0.f);
    }
    if (d < EDIM) agg[s * EDIM + d] = acc;
}

// ---------------- double-buffered 128x128 GEMM, BK=8, f32x2 FMA ----------------
// C[M,128] = A[M,K] @ W[K,128] (+bias)(+residual direct/gather)(+relu)(+col stats)
template <int K, bool BIAS, bool RELU, int RESMODE /*0 none,1 direct,2 gather*/, bool STATS>
__global__ void __launch_bounds__(256, 2) k_gemm(
    const float* __restrict__ A, int aBatch,
    const float* __restrict__ W, int wBatch,
    const float* __restrict__ bias, int biasBatch,
    const float* __restrict__ res, const int* __restrict__ gidx,
    float* __restrict__ C, int cBatch, int cRowStride,
    float* __restrict__ stats, int statsBatch, int M)
{
    constexpr int NST = (K + 7) / 8;
    __shared__ float As[2][8][132];   // padded stride kills store conflicts
    __shared__ float Bs[2][8][128];

    const int tid = threadIdx.x;
    const int tx = tid & 15, ty = tid >> 4;
    const int z = blockIdx.z;
    const float* Ab = A + (size_t)z * aBatch;
    const float* Wb = W + (size_t)z * wBatch;
    float* Cb = C + (size_t)z * cBatch;

    const int row0 = blockIdx.x * 128;
    const int ar = tid >> 1, ac4 = (tid & 1) * 4;
    const int garow = row0 + ar;
    const float* aptr = (garow < M) ? (Ab + (size_t)garow * K) : nullptr;
    const int brow = tid >> 5, bc4 = (tid & 31) * 4;

    float4 aReg = make_float4(0.f, 0.f, 0.f, 0.f);
    float4 bReg = make_float4(0.f, 0.f, 0.f, 0.f);
    if (aptr != nullptr && ac4 < K) aReg = *(const float4*)(aptr + ac4);
    if (brow < K) bReg = *(const float4*)(Wb + (size_t)brow * 128 + bc4);

    float2 acc[8][4];
    #pragma unroll
    for (int i = 0; i < 8; i++)
        #pragma unroll
        for (int j = 0; j < 4; j++) acc[i][j] = make_float2(0.f, 0.f);

    As[0][ac4 + 0][ar] = aReg.x;
    As[0][ac4 + 1][ar] = aReg.y;
    As[0][ac4 + 2][ar] = aReg.z;
    As[0][ac4 + 3][ar] = aReg.w;
    *(float4*)&Bs[0][brow][bc4] = bReg;
    __syncthreads();

    #pragma unroll 1
    for (int s = 0; s < NST; s++) {
        const int cur = s & 1;
        if (s + 1 < NST) {
            const int k0 = (s + 1) * 8;
            aReg = make_float4(0.f, 0.f, 0.f, 0.f);
            bReg = make_float4(0.f, 0.f, 0.f, 0.f);
            if (aptr != nullptr && k0 + ac4 < K) aReg = *(const float4*)(aptr + k0 + ac4);
            if (k0 + brow < K) bReg = *(const float4*)(Wb + (size_t)(k0 + brow) * 128 + bc4);
        }
        #pragma unroll
        for (int kk = 0; kk < 8; kk++) {
            float4 a0 = *(const float4*)&As[cur][kk][ty * 8];
            float4 a1 = *(const float4*)&As[cur][kk][ty * 8 + 4];
            float4 b0 = *(const float4*)&Bs[cur][kk][tx * 8];
            float4 b1 = *(const float4*)&Bs[cur][kk][tx * 8 + 4];
            float aa[8] = {a0.x, a0.y, a0.z, a0.w, a1.x, a1.y, a1.z, a1.w};
            float2 bb[4] = {{b0.x, b0.y}, {b0.z, b0.w}, {b1.x, b1.y}, {b1.z, b1.w}};
            #pragma unroll
            for (int i = 0; i < 8; i++) {
                float2 ai2 = make_float2(aa[i], aa[i]);
                #pragma unroll
                for (int j = 0; j < 4; j++)
                    acc[i][j] = ffma2(ai2, bb[j], acc[i][j]);
            }
        }
        if (s + 1 < NST) {
            const int nxt = cur ^ 1;
            As[nxt][ac4 + 0][ar] = aReg.x;
            As[nxt][ac4 + 1][ar] = aReg.y;
            As[nxt][ac4 + 2][ar] = aReg.z;
            As[nxt][ac4 + 3][ar] = aReg.w;
            *(float4*)&Bs[nxt][brow][bc4] = bReg;
            __syncthreads();
        }
    }

    // ---- epilogue ----
    float colsum[8], colsq[8];
    if (STATS) {
        #pragma unroll
        for (int j = 0; j < 8; j++) { colsum[j] = 0.f; colsq[j] = 0.f; }
    }
    float bv[8];
    if (BIAS) {
        const float* bb = bias + (size_t)z * biasBatch + tx * 8;
        #pragma unroll
        for (int j = 0; j < 8; j++) bv[j] = bb[j];
    }
    #pragma unroll
    for (int i = 0; i < 8; i++) {
        int r = row0 + ty * 8 + i;
        if (r < M) {
            float vals[8];
            #pragma unroll
            for (int j = 0; j < 4; j++) { vals[2*j] = acc[i][j].x; vals[2*j+1] = acc[i][j].y; }
            if (BIAS) {
                #pragma unroll
                for (int j = 0; j < 8; j++) vals[j] += bv[j];
            }
            if (RESMODE != 0) {
                const float* rp;
                if (RESMODE == 1) rp = res + (size_t)r * DIM + tx * 8;
                else { int g = __ldg(&gidx[r]); rp = res + (size_t)g * DIM + tx * 8; }
                float4 r0 = *(const float4*)rp;
                float4 r1 = *(const float4*)(rp + 4);
                vals[0]+=r0.x; vals[1]+=r0.y; vals[2]+=r0.z; vals[3]+=r0.w;
                vals[4]+=r1.x; vals[5]+=r1.y; vals[6]+=r1.z; vals[7]+=r1.w;
            }
            if (RELU) {
                #pragma unroll
                for (int j = 0; j < 8; j++) vals[j] = fmaxf(vals[j], 0.f);
            }
            float* cp = Cb + (size_t)r * cRowStride + tx * 8;
            *(float4*)cp       = make_float4(vals[0], vals[1], vals[2], vals[3]);
            *(float4*)(cp + 4) = make_float4(vals[4], vals[5], vals[6], vals[7]);
            if (STATS) {
                #pragma unroll
                for (int j = 0; j < 8; j++) { colsum[j] += vals[j]; colsq[j] += vals[j] * vals[j]; }
            }
        }
    }
    if (STATS) {
        __syncthreads();                      // done reading tiles; reuse as reduce space
        float* ssum = &As[0][0][0];           // 2048 floats needed (2112 avail)
        float* ssq  = &Bs[0][0][0];           // 2048 floats
        #pragma unroll
        for (int j = 0; j < 8; j++) {
            ssum[ty * 128 + tx * 8 + j] = colsum[j];
            ssq [ty * 128 + tx * 8 + j] = colsq[j];
        }
        __syncthreads();
        if (tid < 128) {
            float s = 0.f, q = 0.f;
            #pragma unroll
            for (int w = 0; w < 16; w++) {
                s += ssum[w * 128 + tid];
                q += ssq [w * 128 + tid];
            }
            float* st = stats + (size_t)z * statsBatch;
            atomicAdd(&st[tid], s);
            atomicAdd(&st[128 + tid], q);
        }
    }
}

// ---------------- BN finalize / apply ----------------
__global__ void k_bnfin(const float* __restrict__ stats, const float* __restrict__ gamma,
                        const float* __restrict__ beta, float invM,
                        float* scale, float* shift, int G) {
    int i = blockIdx.x * blockDim.x + threadIdx.x;
    if (i >= G * 128) return;
    int g = i / 128, c = i % 128;
    float mean = stats[g * 256 + c] * invM;
    float ex2  = stats[g * 256 + 128 + c] * invM;
    float var = ex2 - mean * mean;
    float s = gamma[i] * rsqrtf(var + BN_EPS);
    scale[i] = s;
    shift[i] = beta[i] - mean * s;
}

__global__ void k_bnrelu(float* t, const float* __restrict__ scale, const float* __restrict__ shift) {
    int i = blockIdx.x * blockDim.x + threadIdx.x;
    const int total = 3 * NSRC * (DIM / 4);
    if (i >= total) return;
    int c4 = i & 31;
    int z = i / (NSRC * 32);
    float4 v = ((float4*)t)[i];
    float4 sc = ((const float4*)scale)[z * 32 + c4];
    float4 sh = ((const float4*)shift)[z * 32 + c4];
    v.x = fmaxf(v.x * sc.x + sh.x, 0.f);
    v.y = fmaxf(v.y * sc.y + sh.y, 0.f);
    v.z = fmaxf(v.z * sc.z + sh.z, 0.f);
    v.w = fmaxf(v.w * sc.w + sh.w, 0.f);
    ((float4*)t)[i] = v;
}

__global__ void k_pebias(const float* a, const float* b, float* o) {
    int i = threadIdx.x;
    if (i < DIM) o[i] = a[i] + b[i];
}

// ---------------- score (BN+relu+dot fused) ----------------
__global__ void k_score(const float* __restrict__ hpath, const float* __restrict__ scale,
                        const float* __restrict__ shift, const float* __restrict__ sw,
                        float* __restrict__ scores) {
    int gt = blockIdx.x * blockDim.x + threadIdx.x;
    int e = gt >> 5, lane = gt & 31;
    if (e >= NEDGE) return;
    float4 h = ((const float4*)(hpath + (size_t)e * DIM))[lane];
    float4 sc = __ldg(&((const float4*)scale)[lane]);
    float4 sh = __ldg(&((const float4*)shift)[lane]);
    float4 w  = __ldg(&((const float4*)sw)[lane]);
    float s = fmaxf(h.x * sc.x + sh.x, 0.f) * w.x
            + fmaxf(h.y * sc.y + sh.y, 0.f) * w.y
            + fmaxf(h.z * sc.z + sh.z, 0.f) * w.z
            + fmaxf(h.w * sc.w + sh.w, 0.f) * w.w;
    #pragma unroll
    for (int o = 16; o > 0; o >>= 1) s += __shfl_xor_sync(~0u, s, o);
    if (lane == 0) scores[e] = s;
}

// ---------------- top-k (value desc, index asc) ----------------
__device__ __forceinline__ bool kbetter(float a, int ia, float b, int ib) {
    return (a > b) || (a == b && ia < ib);
}

__device__ __forceinline__ void kmerge(const float* av, const int* ai,
                                       const float* bv, const int* bi,
                                       float* ov, int* oi) {
    int x = 0, y = 0;
    for (int k = 0; k < TOPN; k++) {
        if (kbetter(av[x], ai[x], bv[y], bi[y])) { ov[k] = av[x]; oi[k] = ai[x]; x++; }
        else                                      { ov[k] = bv[y]; oi[k] = bi[y]; y++; }
    }
}

__device__ __forceinline__ void block_topk_reduce(float* v, int* id, float* sv, int* si,
                                                  int t) {
    for (int k = 0; k < TOPN; k++) { sv[t * TOPN + k] = v[k]; si[t * TOPN + k] = id[k]; }
    __syncthreads();
    for (int strd = 128; strd > 0; strd >>= 1) {
        if (t < strd) {
            float av[TOPN], bv[TOPN], ov[TOPN];
            int ai[TOPN], bi[TOPN], oi[TOPN];
            for (int k = 0; k < TOPN; k++) {
                av[k] = sv[t * TOPN + k];            ai[k] = si[t * TOPN + k];
                bv[k] = sv[(t + strd) * TOPN + k];   bi[k] = si[(t + strd) * TOPN + k];
            }
            kmerge(av, ai, bv, bi, ov, oi);
            for (int k = 0; k < TOPN; k++) { sv[t * TOPN + k] = ov[k]; si[t * TOPN + k] = oi[k]; }
        }
        __syncthreads();
    }
}

__global__ void k_top1(const float* __restrict__ scores, float* cv, int* ci) {
    __shared__ float sv[256 * TOPN];
    __shared__ int   si[256 * TOPN];
    const float NEG = __int_as_float(0xff800000);  // -inf
    float v[TOPN]; int id[TOPN];
    for (int k = 0; k < TOPN; k++) { v[k] = NEG; id[k] = 0x7fffffff; }
    int stride = gridDim.x * blockDim.x;
    for (int i = blockIdx.x * blockDim.x + threadIdx.x; i < NEDGE; i += stride) {
        float s = scores[i];
        if (kbetter(s, i, v[TOPN - 1], id[TOPN - 1])) {
            int p = TOPN - 1;
            while (p > 0 && kbetter(s, i, v[p - 1], id[p - 1])) {
                v[p] = v[p - 1]; id[p] = id[p - 1]; p--;
            }
            v[p] = s; id[p] = i;
        }
    }
    block_topk_reduce(v, id, sv, si, threadIdx.x);
    if (threadIdx.x == 0)
        for (int k = 0; k < TOPN; k++) {
            cv[blockIdx.x * TOPN + k] = sv[k];
            ci[blockIdx.x * TOPN + k] = si[k];
        }
}

__global__ void k_top2(const float* __restrict__ cv, const int* __restrict__ ci, float* out) {
    __shared__ float sv[256 * TOPN];
    __shared__ int   si[256 * TOPN];
    int t = threadIdx.x;
    float v[TOPN]; int id[TOPN];
    for (int k = 0; k < TOPN; k++) { v[k] = cv[t * TOPN + k]; id[k] = ci[t * TOPN + k]; }
    block_topk_reduce(v, id, sv, si, t);
    if (t == 0)
        for (int k = 0; k < TOPN; k++) {
            out[k]        = sv[k];
            out[TOPN + k] = (float)si[k];
        }
}

// ---------------- launch ----------------
extern "C" void kernel_launch(void* const* d_in, const int* in_sizes, int n_in,
                              void* d_out, int out_size) {
    const float* F[20];
    for (int i = 0; i < 20 && i < n_in; i++) F[i] = (const float*)d_in[i];

    const float *paths_srcs, *path_feats, *conv_edge_W, *conv_edge_b, *conv_W1,
                *conv_bn_g, *conv_bn_b, *conv_W2, *lin1_W, *lin1_b, *lin2_W, *lin2_b,
                *pe_src_W, *pe_src_b, *pe_tgt_W, *pe_tgt_b, *pe_bn_g, *pe_bn_b, *score_w;
    const int* src_ids;

    if (in_sizes[2] == NEDGE) {  // setup_inputs dict order (src_ids third)
        paths_srcs = F[0]; path_feats = F[1]; src_ids = (const int*)d_in[2];
        conv_edge_W = F[3]; conv_edge_b = F[4]; conv_W1 = F[5];
        conv_bn_g = F[6]; conv_bn_b = F[7]; conv_W2 = F[8];
        lin1_W = F[9]; lin1_b = F[10]; lin2_W = F[11]; lin2_b = F[12];
        pe_src_W = F[13]; pe_src_b = F[14]; pe_tgt_W = F[15]; pe_tgt_b = F[16];
        pe_bn_g = F[17]; pe_bn_b = F[18]; score_w = F[19];
    } else {                     // reference() signature order (src_ids last)
        paths_srcs = F[0]; path_feats = F[1];
        conv_edge_W = F[2]; conv_edge_b = F[3]; conv_W1 = F[4];
        conv_bn_g = F[5]; conv_bn_b = F[6]; conv_W2 = F[7];
        lin1_W = F[8]; lin1_b = F[9]; lin2_W = F[10]; lin2_b = F[11];
        pe_src_W = F[12]; pe_src_b = F[13]; pe_tgt_W = F[14]; pe_tgt_b = F[15];
        pe_bn_g = F[16]; pe_bn_b = F[17]; score_w = F[18];
        src_ids = (const int*)d_in[19];
    }

    auto sym = [](const void* s) { void* p = nullptr; cudaGetSymbolAddress(&p, s); return p; };
    float* agg      = (float*)sym(d_agg);
    float* h        = (float*)sym(d_h);
    float* t        = (float*)sym(d_t);
    float* hcat     = (float*)sym(d_hcat);
    float* tmp      = (float*)sym(d_tmp);
    float* nodeproj = (float*)sym(d_nodeproj);
    float* hpath    = (float*)sym(d_hpath);
    float* scores   = (float*)sym(d_scores);
    float* stats    = (float*)sym(d_stats);
    float* bns      = (float*)sym(d_bns);
    float* bnsh     = (float*)sym(d_bnsh);
    float* pebias   = (float*)sym(d_pebias);
    int*   cnt      = (int*)sym(d_cnt);
    int*   off      = (int*)sym(d_off);
    int*   cursor   = (int*)sym(d_cursor);
    int*   elist    = (int*)sym(d_elist);
    float* cv       = (float*)sym(d_cv);
    int*   ci       = (int*)sym(d_ci);
    float* out      = (float*)d_out;

    const dim3 blk(256);
    const int NODE_BLKS = (NSRC + 127) / 128;    // 79
    const int EDGE_BLKS = NEDGE / 128;           // 2500

    // 1) CSR build + segment sum of relu(path_feats)
    k_zero<<<(NSRC + 255) / 256, blk>>>(cnt, stats);
    k_hist<<<(NEDGE + 255) / 256, blk>>>(src_ids, cnt);
    k_scan<<<1, 1024>>>(cnt, off, cursor);
    k_scatter<<<(NEDGE + 255) / 256, blk>>>(src_ids, cursor, elist);
    k_agg<<<NSRC, blk>>>(path_feats, elist, off, agg);

    // 2) h_i = agg @ We_i + be_i + paths_srcs   (batched over i)
    k_gemm<236, true, false, 1, false><<<dim3(NODE_BLKS, 1, 3), blk>>>(
        agg, 0, conv_edge_W, 236 * 128, conv_edge_b, 128,
        paths_srcs, nullptr, h, NSRC * DIM, DIM, nullptr, 0, NSRC);

    // 3) t_i = h_i @ W1_i  with fused BN stats
    k_gemm<128, false, false, 0, true><<<dim3(NODE_BLKS, 1, 3), blk>>>(
        h, NSRC * DIM, conv_W1, DIM * DIM, nullptr, 0,
        nullptr, nullptr, t, NSRC * DIM, DIM, stats, 256, NSRC);

    // 4) BN finalize (3 conv groups) + apply BN+relu in place
    k_bnfin<<<2, blk>>>(stats, conv_bn_g, conv_bn_b, 1.f / NSRC, bns, bnsh, 3);
    k_bnrelu<<<(3 * NSRC * 32 + 255) / 256, blk>>>(t, bns, bnsh);

    // 5) hs_i = z_i @ W2_i  -> hcat columns [i*128, i*128+128)
    k_gemm<128, false, false, 0, false><<<dim3(NODE_BLKS, 1, 3), blk>>>(
        t, NSRC * DIM, conv_W2, DIM * DIM, nullptr, 0,
        nullptr, nullptr, hcat, 128, 3 * DIM, nullptr, 0, NSRC);

    // 6) lin1 (relu) and lin2 -> node_emb directly into d_out
    k_gemm<384, true, true, 0, false><<<dim3(NODE_BLKS, 1, 1), blk>>>(
        hcat, 0, lin1_W, 0, lin1_b, 0, nullptr, nullptr, tmp, 0, DIM, nullptr, 0, NSRC);
    k_gemm<128, true, false, 0, false><<<dim3(NODE_BLKS, 1, 1), blk>>>(
        tmp, 0, lin2_W, 0, lin2_b, 0, nullptr, nullptr, out, 0, DIM, nullptr, 0, NSRC);

    // 7) node_proj = node_emb @ pe_src_W + (pe_src_b + pe_tgt_b)
    k_pebias<<<1, 128>>>(pe_src_b, pe_tgt_b, pebias);
    k_gemm<128, true, false, 0, false><<<dim3(NODE_BLKS, 1, 1), blk>>>(
        out, 0, pe_src_W, 0, pebias, 0, nullptr, nullptr, nodeproj, 0, DIM, nullptr, 0, NSRC);

    // 8) hpath = path_feats @ pe_tgt_W + node_proj[src]   (fused gather + BN stats)
    k_gemm<236, false, false, 2, true><<<dim3(EDGE_BLKS, 1, 1), blk>>>(
        path_feats, 0, pe_tgt_W, 0, nullptr, 0,
        nodeproj, src_ids, hpath, 0, DIM, stats + 768, 0, NEDGE);

    // 9) pe BN finalize, fused BN+relu+dot(score_w)
    k_bnfin<<<1, 128>>>(stats + 768, pe_bn_g, pe_bn_b, 1.f / NEDGE, bns + 384, bnsh + 384, 1);
    k_score<<<(NEDGE * 32 + 255) / 256, blk>>>(hpath, bns + 384, bnsh + 384, score_w, scores);

    // 10) top-6 (two-stage block merge), write tail of d_out
    k_top1<<<256, blk>>>(scores, cv, ci);
    k_top2<<<1, blk>>>(cv, ci, out + (size_t)NSRC * DIM);
}

// round 13
// speedup vs baseline: 2.1356x; 1.2779x over previous
#include <cuda_runtime.h>
#include <cuda_bf16.h>
#include <cstdint>
#include <math.h>

// ---------------- problem constants ----------------
constexpr int NSRC  = 10000;
constexpr int NEDGE = 320000;
constexpr int DIM   = 128;
constexpr int EDIM  = 236;
constexpr int TOPN  = 6;
constexpr float BN_EPS = 1e-5f;

// ---------------- static device scratch ----------------
__device__ float d_agg[NSRC * EDIM];
__device__ float d_h[3 * NSRC * DIM];
__device__ float d_t[3 * NSRC * DIM];
__device__ float d_hcat[NSRC * 3 * DIM];
__device__ float d_tmp[NSRC * DIM];
__device__ float d_nodeproj[NSRC * DIM];
__device__ float d_hpath[(size_t)NEDGE * DIM];
__device__ float d_scores[NEDGE];
__device__ float d_stats[1024];
__device__ float d_bns[512];
__device__ float d_bnsh[512];
__device__ float d_pebias[DIM];
__device__ int   d_cnt[NSRC];
__device__ int   d_off[NSRC + 1];
__device__ int   d_cursor[NSRC];
__device__ int   d_elist[NEDGE];
__device__ float d_cv[256 * TOPN];
__device__ int   d_ci[256 * TOPN];
// split-bf16 images of pe_tgt_W: [n=128][k=240] row-major (k contiguous)
__device__ __align__(16) unsigned short d_bhi[128 * 240];
__device__ __align__(16) unsigned short d_blo[128 * 240];

// ---------------- packed f32x2 FMA ----------------
union F2LL { float2 f2; unsigned long long ll; };
__device__ __forceinline__ float2 ffma2(float2 a, float2 b, float2 c) {
    F2LL ua, ub, uc, ud;
    ua.f2 = a; ub.f2 = b; uc.f2 = c;
    asm("fma.rn.f32x2 %0, %1, %2, %3;"
        : "=l"(ud.ll) : "l"(ua.ll), "l"(ub.ll), "l"(uc.ll));
    return ud.f2;
}

// ---------------- warp-level tensor core helpers (generic PTX, sm_80+) ----------------
__device__ __forceinline__ uint32_t smem_u32(const void* p) {
    uint32_t a;
    asm("{ .reg .u64 t; cvta.to.shared.u64 t, %1; cvt.u32.u64 %0, t; }" : "=r"(a) : "l"(p));
    return a;
}
__device__ __forceinline__ void ldmx4(uint32_t* r, uint32_t addr) {
    asm volatile("ldmatrix.sync.aligned.m8n8.x4.shared.b16 {%0,%1,%2,%3}, [%4];"
        : "=r"(r[0]), "=r"(r[1]), "=r"(r[2]), "=r"(r[3]) : "r"(addr));
}
__device__ __forceinline__ void mma16816(float* c, const uint32_t* a, const uint32_t* b) {
    asm volatile(
        "mma.sync.aligned.m16n8k16.row.col.f32.bf16.bf16.f32 "
        "{%0,%1,%2,%3}, {%4,%5,%6,%7}, {%8,%9}, {%0,%1,%2,%3};"
        : "+f"(c[0]), "+f"(c[1]), "+f"(c[2]), "+f"(c[3])
        : "r"(a[0]), "r"(a[1]), "r"(a[2]), "r"(a[3]), "r"(b[0]), "r"(b[1]));
}

// ---------------- CSR build ----------------
__global__ void k_zero(int* cnt, float* stats) {
    int i = blockIdx.x * blockDim.x + threadIdx.x;
    if (i < NSRC) cnt[i] = 0;
    if (i < 1024) stats[i] = 0.f;
}

__global__ void k_hist(const int* __restrict__ src, int* cnt) {
    int i = blockIdx.x * blockDim.x + threadIdx.x;
    if (i < NEDGE) atomicAdd(&cnt[src[i]], 1);
}

__global__ void k_scan(const int* __restrict__ cnt, int* off, int* cursor) {
    __shared__ int warp_sums[32];
    __shared__ int s_carry;
    if (threadIdx.x == 0) s_carry = 0;
    __syncthreads();
    const int lane = threadIdx.x & 31, wid = threadIdx.x >> 5;
    for (int base = 0; base < NSRC; base += blockDim.x) {
        int i = base + threadIdx.x;
        int v = (i < NSRC) ? cnt[i] : 0;
        int x = v;
        #pragma unroll
        for (int d = 1; d < 32; d <<= 1) {
            int y = __shfl_up_sync(~0u, x, d);
            if (lane >= d) x += y;
        }
        if (lane == 31) warp_sums[wid] = x;
        __syncthreads();
        if (wid == 0) {
            int w = warp_sums[lane];
            #pragma unroll
            for (int d = 1; d < 32; d <<= 1) {
                int y = __shfl_up_sync(~0u, w, d);
                if (lane >= d) w += y;
            }
            warp_sums[lane] = w;
        }
        __syncthreads();
        int warp_off = (wid == 0) ? 0 : warp_sums[wid - 1];
        int excl = s_carry + warp_off + x - v;
        if (i < NSRC) { off[i] = excl; cursor[i] = excl; }
        __syncthreads();
        if (threadIdx.x == blockDim.x - 1) s_carry += warp_off + x;
        __syncthreads();
    }
    if (threadIdx.x == 0) off[NSRC] = s_carry;
}

__global__ void k_scatter(const int* __restrict__ src, int* cursor, int* elist) {
    int e = blockIdx.x * blockDim.x + threadIdx.x;
    if (e < NEDGE) {
        int p = atomicAdd(&cursor[src[e]], 1);
        elist[p] = e;
    }
}

__global__ void k_agg(const float* __restrict__ pf, const int* __restrict__ elist,
                      const int* __restrict__ off, float* __restrict__ agg) {
    int s = blockIdx.x;
    int d = threadIdx.x;
    int beg = off[s], end = off[s + 1];
    float acc = 0.f;
    int p = beg;
    for (; p + 3 < end; p += 4) {
        int e0 = __ldg(&elist[p]),     e1 = __ldg(&elist[p + 1]);
        int e2 = __ldg(&elist[p + 2]), e3 = __ldg(&elist[p + 3]);
        if (d < EDIM) {
            float v0 = __ldg(&pf[(size_t)e0 * EDIM + d]);
            float v1 = __ldg(&pf[(size_t)e1 * EDIM + d]);
            float v2 = __ldg(&pf[(size_t)e2 * EDIM + d]);
            float v3 = __ldg(&pf[(size_t)e3 * EDIM + d]);
            acc += fmaxf(v0, 0.f) + fmaxf(v1, 0.f) + fmaxf(v2, 0.f) + fmaxf(v3, 0.f);
        }
    }
    for (; p < end; p++) {
        int e = __ldg(&elist[p]);
        if (d < EDIM) acc += fmaxf(__ldg(&pf[(size_t)e * EDIM + d]), 0.f);
    }
    if (d < EDIM) agg[s * EDIM + d] = acc;
}

// ---------------- node-side GEMM (FFMA2 double-buffered, proven R7) ----------------
template <int K, bool BIAS, bool RELU, int RESMODE, bool STATS>
__global__ void __launch_bounds__(256, 2) k_gemm(
    const float* __restrict__ A, int aBatch,
    const float* __restrict__ W, int wBatch,
    const float* __restrict__ bias, int biasBatch,
    const float* __restrict__ res, const int* __restrict__ gidx,
    float* __restrict__ C, int cBatch, int cRowStride,
    float* __restrict__ stats, int statsBatch, int M)
{
    constexpr int NST = (K + 7) / 8;
    __shared__ float As[2][8][132];
    __shared__ float Bs[2][8][128];

    const int tid = threadIdx.x;
    const int tx = tid & 15, ty = tid >> 4;
    const int z = blockIdx.z;
    const float* Ab = A + (size_t)z * aBatch;
    const float* Wb = W + (size_t)z * wBatch;
    float* Cb = C + (size_t)z * cBatch;

    const int row0 = blockIdx.x * 128;
    const int ar = tid >> 1, ac4 = (tid & 1) * 4;
    const int garow = row0 + ar;
    const float* aptr = (garow < M) ? (Ab + (size_t)garow * K) : nullptr;
    const int brow = tid >> 5, bc4 = (tid & 31) * 4;

    float4 aReg = make_float4(0.f, 0.f, 0.f, 0.f);
    float4 bReg = make_float4(0.f, 0.f, 0.f, 0.f);
    if (aptr != nullptr && ac4 < K) aReg = *(const float4*)(aptr + ac4);
    if (brow < K) bReg = *(const float4*)(Wb + (size_t)brow * 128 + bc4);

    float2 acc[8][4];
    #pragma unroll
    for (int i = 0; i < 8; i++)
        #pragma unroll
        for (int j = 0; j < 4; j++) acc[i][j] = make_float2(0.f, 0.f);

    As[0][ac4 + 0][ar] = aReg.x;
    As[0][ac4 + 1][ar] = aReg.y;
    As[0][ac4 + 2][ar] = aReg.z;
    As[0][ac4 + 3][ar] = aReg.w;
    *(float4*)&Bs[0][brow][bc4] = bReg;
    __syncthreads();

    #pragma unroll 1
    for (int s = 0; s < NST; s++) {
        const int cur = s & 1;
        if (s + 1 < NST) {
            const int k0 = (s + 1) * 8;
            aReg = make_float4(0.f, 0.f, 0.f, 0.f);
            bReg = make_float4(0.f, 0.f, 0.f, 0.f);
            if (aptr != nullptr && k0 + ac4 < K) aReg = *(const float4*)(aptr + k0 + ac4);
            if (k0 + brow < K) bReg = *(const float4*)(Wb + (size_t)(k0 + brow) * 128 + bc4);
        }
        #pragma unroll
        for (int kk = 0; kk < 8; kk++) {
            float4 a0 = *(const float4*)&As[cur][kk][ty * 8];
            float4 a1 = *(const float4*)&As[cur][kk][ty * 8 + 4];
            float4 b0 = *(const float4*)&Bs[cur][kk][tx * 8];
            float4 b1 = *(const float4*)&Bs[cur][kk][tx * 8 + 4];
            float aa[8] = {a0.x, a0.y, a0.z, a0.w, a1.x, a1.y, a1.z, a1.w};
            float2 bb[4] = {{b0.x, b0.y}, {b0.z, b0.w}, {b1.x, b1.y}, {b1.z, b1.w}};
            #pragma unroll
            for (int i = 0; i < 8; i++) {
                float2 ai2 = make_float2(aa[i], aa[i]);
                #pragma unroll
                for (int j = 0; j < 4; j++)
                    acc[i][j] = ffma2(ai2, bb[j], acc[i][j]);
            }
        }
        if (s + 1 < NST) {
            const int nxt = cur ^ 1;
            As[nxt][ac4 + 0][ar] = aReg.x;
            As[nxt][ac4 + 1][ar] = aReg.y;
            As[nxt][ac4 + 2][ar] = aReg.z;
            As[nxt][ac4 + 3][ar] = aReg.w;
            *(float4*)&Bs[nxt][brow][bc4] = bReg;
            __syncthreads();
        }
    }

    float colsum[8], colsq[8];
    if (STATS) {
        #pragma unroll
        for (int j = 0; j < 8; j++) { colsum[j] = 0.f; colsq[j] = 0.f; }
    }
    float bv[8];
    if (BIAS) {
        const float* bb = bias + (size_t)z * biasBatch + tx * 8;
        #pragma unroll
        for (int j = 0; j < 8; j++) bv[j] = bb[j];
    }
    #pragma unroll
    for (int i = 0; i < 8; i++) {
        int r = row0 + ty * 8 + i;
        if (r < M) {
            float vals[8];
            #pragma unroll
            for (int j = 0; j < 4; j++) { vals[2*j] = acc[i][j].x; vals[2*j+1] = acc[i][j].y; }
            if (BIAS) {
                #pragma unroll
                for (int j = 0; j < 8; j++) vals[j] += bv[j];
            }
            if (RESMODE != 0) {
                const float* rp;
                if (RESMODE == 1) rp = res + (size_t)r * DIM + tx * 8;
                else { int g = __ldg(&gidx[r]); rp = res + (size_t)g * DIM + tx * 8; }
                float4 r0 = *(const float4*)rp;
                float4 r1 = *(const float4*)(rp + 4);
                vals[0]+=r0.x; vals[1]+=r0.y; vals[2]+=r0.z; vals[3]+=r0.w;
                vals[4]+=r1.x; vals[5]+=r1.y; vals[6]+=r1.z; vals[7]+=r1.w;
            }
            if (RELU) {
                #pragma unroll
                for (int j = 0; j < 8; j++) vals[j] = fmaxf(vals[j], 0.f);
            }
            float* cp = Cb + (size_t)r * cRowStride + tx * 8;
            *(float4*)cp       = make_float4(vals[0], vals[1], vals[2], vals[3]);
            *(float4*)(cp + 4) = make_float4(vals[4], vals[5], vals[6], vals[7]);
            if (STATS) {
                #pragma unroll
                for (int j = 0; j < 8; j++) { colsum[j] += vals[j]; colsq[j] += vals[j] * vals[j]; }
            }
        }
    }
    if (STATS) {
        __syncthreads();
        float* ssum = &As[0][0][0];
        float* ssq  = &Bs[0][0][0];
        #pragma unroll
        for (int j = 0; j < 8; j++) {
            ssum[ty * 128 + tx * 8 + j] = colsum[j];
            ssq [ty * 128 + tx * 8 + j] = colsq[j];
        }
        __syncthreads();
        if (tid < 128) {
            float s = 0.f, q = 0.f;
            #pragma unroll
            for (int w = 0; w < 16; w++) {
                s += ssum[w * 128 + tid];
                q += ssq [w * 128 + tid];
            }
            float* st = stats + (size_t)z * statsBatch;
            atomicAdd(&st[tid], s);
            atomicAdd(&st[128 + tid], q);
        }
    }
}

// ---------------- W split: pe_tgt_W[236,128] -> Bhi/Blo [n=128][k=240] bf16 ----------------
__global__ void k_wconv(const float* __restrict__ W, unsigned short* bhi, unsigned short* blo) {
    int i = blockIdx.x * blockDim.x + threadIdx.x;
    if (i >= 128 * 240) return;
    int n = i / 240, k = i % 240;
    float x = (k < EDIM) ? W[k * 128 + n] : 0.f;
    __nv_bfloat16 h = __float2bfloat16(x);
    float lof = x - __bfloat162float(h);
    __nv_bfloat16 l = __float2bfloat16(lof);
    bhi[i] = *reinterpret_cast<unsigned short*>(&h);
    blo[i] = *reinterpret_cast<unsigned short*>(&l);
}

// ---------------- big edge GEMM: mma.sync split-bf16, persistent CTAs ----------------
// hpath[320000,128] = path_feats[320000,236] @ pe_tgt_W[236,128] + nodeproj[src_ids]
constexpr int B_STRIDE_B = 496;   // bytes per n-row in smem (248 bf16, conflict-free)
constexpr int A_STRIDE_B = 176;   // bytes per m-row in smem (88 bf16, conflict-free)
constexpr int SM_BH = 0;
constexpr int SM_BL = 128 * B_STRIDE_B;            // 63488
constexpr int SM_AH = 2 * 128 * B_STRIDE_B;        // 126976
constexpr int SM_AL = SM_AH + 128 * A_STRIDE_B;    // 149504
constexpr int SMEM_PG = SM_AL + 128 * A_STRIDE_B;  // 172032

__device__ __forceinline__ void cvt8(const float4 a, const float4 b,
                                     uint32_t hi4[4], uint32_t lo4[4]) {
    float xs[8] = {a.x, a.y, a.z, a.w, b.x, b.y, b.z, b.w};
    float ls[8];
    #pragma unroll
    for (int i = 0; i < 4; i++) {
        __nv_bfloat162 h = __floats2bfloat162_rn(xs[2*i], xs[2*i+1]);
        ls[2*i]   = xs[2*i]   - __bfloat162float(h.x);
        ls[2*i+1] = xs[2*i+1] - __bfloat162float(h.y);
        hi4[i] = *reinterpret_cast<uint32_t*>(&h);
    }
    #pragma unroll
    for (int i = 0; i < 4; i++) {
        __nv_bfloat162 l = __floats2bfloat162_rn(ls[2*i], ls[2*i+1]);
        lo4[i] = *reinterpret_cast<uint32_t*>(&l);
    }
}

__global__ void __launch_bounds__(256, 1) k_pathgemm(
    const float* __restrict__ pf,
    const unsigned short* __restrict__ gbhi,
    const unsigned short* __restrict__ gblo,
    const float* __restrict__ nodeproj,
    const int* __restrict__ gidx,
    float* __restrict__ hpath)
{
    extern __shared__ char smemc[];
    const uint32_t sb = smem_u32(smemc);
    const int tid = threadIdx.x, wid = tid >> 5, lane = tid & 31;

    // copy B (hi+lo) into smem with re-stride 480B -> 496B rows (once per CTA)
    for (int i = tid; i < 128 * 30; i += 256) {
        int row = i / 30, j = i % 30;
        *(uint4*)(smemc + SM_BH + row * B_STRIDE_B + j * 16) = ((const uint4*)gbhi)[i];
        *(uint4*)(smemc + SM_BL + row * B_STRIDE_B + j * 16) = ((const uint4*)gblo)[i];
    }
    __syncthreads();

    const int warp_m = (wid >> 2) * 64;     // 0 or 64
    const int warp_n = (wid & 3) * 32;      // 0,32,64,96
    const int row_c = tid >> 1, half = tid & 1;   // conversion: thread -> (row, k-half)

    for (int tile = blockIdx.x; tile < NEDGE / 128; tile += gridDim.x) {
        float acc[4][4][4];
        #pragma unroll
        for (int mi = 0; mi < 4; mi++)
            #pragma unroll
            for (int ni = 0; ni < 4; ni++)
                #pragma unroll
                for (int q = 0; q < 4; q++) acc[mi][ni][q] = 0.f;

        const float* prow = pf + (size_t)(tile * 128 + row_c) * EDIM;

        #pragma unroll 1
        for (int ch = 0; ch < 3; ch++) {
            // convert 80-K chunk (this thread: 40 cols) into smem hi/lo
            #pragma unroll
            for (int g = 0; g < 5; g++) {
                int kl = half * 40 + g * 8;
                int kg = ch * 80 + kl;
                float4 va = (kg     < EDIM) ? *(const float4*)(prow + kg)     : make_float4(0,0,0,0);
                float4 vb = (kg + 4 < EDIM) ? *(const float4*)(prow + kg + 4) : make_float4(0,0,0,0);
                uint32_t hi4[4], lo4[4];
                cvt8(va, vb, hi4, lo4);
                int off = row_c * A_STRIDE_B + kl * 2;
                *(uint4*)(smemc + SM_AH + off) = make_uint4(hi4[0], hi4[1], hi4[2], hi4[3]);
                *(uint4*)(smemc + SM_AL + off) = make_uint4(lo4[0], lo4[1], lo4[2], lo4[3]);
            }
            __syncthreads();

            #pragma unroll
            for (int ks = 0; ks < 5; ks++) {
                const int k0 = ks * 16;
                // A smem holds only the current chunk -> local k offset
                const int koff2a = (k0 + (lane >> 4) * 8) * 2;
                // B smem holds all 240 K -> GLOBAL k offset (ch*80 + local)  [R11 bugfix]
                const int koff2b = (ch * 80 + k0 + (lane >> 4) * 8) * 2;
                uint32_t aH[4][4], aL[4][4], bH[2][4], bL[2][4];
                const int arow = warp_m + (lane & 15);
                #pragma unroll
                for (int mi = 0; mi < 4; mi++) {
                    uint32_t ad = sb + SM_AH + (arow + mi * 16) * A_STRIDE_B + koff2a;
                    ldmx4(aH[mi], ad);
                    ldmx4(aL[mi], ad + (SM_AL - SM_AH));
                }
                const int bn = warp_n + (lane & 15);
                #pragma unroll
                for (int bi = 0; bi < 2; bi++) {
                    uint32_t bd = sb + SM_BH + (bn + bi * 16) * B_STRIDE_B + koff2b;
                    ldmx4(bH[bi], bd);
                    ldmx4(bL[bi], bd + SM_BL);
                }
                #pragma unroll
                for (int mi = 0; mi < 4; mi++)
                    #pragma unroll
                    for (int ni = 0; ni < 4; ni++) {
                        uint32_t bh2[2] = { bH[ni >> 1][ni & 1], bH[ni >> 1][2 + (ni & 1)] };
                        uint32_t bl2[2] = { bL[ni >> 1][ni & 1], bL[ni >> 1][2 + (ni & 1)] };
                        mma16816(acc[mi][ni], aH[mi], bh2);
                        mma16816(acc[mi][ni], aH[mi], bl2);
                        mma16816(acc[mi][ni], aL[mi], bh2);
                    }
            }
            __syncthreads();
        }

        // epilogue: acc + nodeproj[src] -> hpath
        const int r_base = tile * 128 + warp_m;
        #pragma unroll
        for (int mi = 0; mi < 4; mi++) {
            int r0 = r_base + mi * 16 + (lane >> 2);
            int r1 = r0 + 8;
            int g0 = __ldg(&gidx[r0]), g1 = __ldg(&gidx[r1]);
            const float* np0 = nodeproj + (size_t)g0 * 128;
            const float* np1 = nodeproj + (size_t)g1 * 128;
            float* hp0 = hpath + (size_t)r0 * 128;
            float* hp1 = hpath + (size_t)r1 * 128;
            int cb = warp_n + 2 * (lane & 3);
            #pragma unroll
            for (int ni = 0; ni < 4; ni++) {
                int col = cb + ni * 8;
                float2 e0 = *(const float2*)(np0 + col);
                float2 e1 = *(const float2*)(np1 + col);
                *(float2*)(hp0 + col) = make_float2(acc[mi][ni][0] + e0.x, acc[mi][ni][1] + e0.y);
                *(float2*)(hp1 + col) = make_float2(acc[mi][ni][2] + e1.x, acc[mi][ni][3] + e1.y);
            }
        }
    }
}

// ---------------- hpath column stats (sum, sumsq) ----------------
__global__ void k_colstats(const float* __restrict__ hpath, float* __restrict__ stats) {
    __shared__ float ss[8][128], sq[8][128];
    int w = threadIdx.x >> 5, lane = threadIdx.x & 31;
    int wglobal = blockIdx.x * 8 + w;
    int nw = gridDim.x * 8;
    float4 s = make_float4(0, 0, 0, 0), q = make_float4(0, 0, 0, 0);
    for (int r = wglobal; r < NEDGE; r += nw) {
        float4 v = ((const float4*)(hpath + (size_t)r * 128))[lane];
        s.x += v.x; s.y += v.y; s.z += v.z; s.w += v.w;
        q.x += v.x * v.x; q.y += v.y * v.y; q.z += v.z * v.z; q.w += v.w * v.w;
    }
    ((float4*)ss[w])[lane] = s;
    ((float4*)sq[w])[lane] = q;
    __syncthreads();
    if (threadIdx.x < 128) {
        float a = 0.f, b = 0.f;
        #pragma unroll
        for (int i = 0; i < 8; i++) { a += ss[i][threadIdx.x]; b += sq[i][threadIdx.x]; }
        atomicAdd(&stats[threadIdx.x], a);
        atomicAdd(&stats[128 + threadIdx.x], b);
    }
}

// ---------------- BN finalize / apply ----------------
__global__ void k_bnfin(const float* __restrict__ stats, const float* __restrict__ gamma,
                        const float* __restrict__ beta, float invM,
                        float* scale, float* shift, int G) {
    int i = blockIdx.x * blockDim.x + threadIdx.x;
    if (i >= G * 128) return;
    int g = i / 128, c = i % 128;
    float mean = stats[g * 256 + c] * invM;
    float ex2  = stats[g * 256 + 128 + c] * invM;
    float var = ex2 - mean * mean;
    float s = gamma[i] * rsqrtf(var + BN_EPS);
    scale[i] = s;
    shift[i] = beta[i] - mean * s;
}

__global__ void k_bnrelu(float* t, const float* __restrict__ scale, const float* __restrict__ shift) {
    int i = blockIdx.x * blockDim.x + threadIdx.x;
    const int total = 3 * NSRC * (DIM / 4);
    if (i >= total) return;
    int c4 = i & 31;
    int z = i / (NSRC * 32);
    float4 v = ((float4*)t)[i];
    float4 sc = ((const float4*)scale)[z * 32 + c4];
    float4 sh = ((const float4*)shift)[z * 32 + c4];
    v.x = fmaxf(v.x * sc.x + sh.x, 0.f);
    v.y = fmaxf(v.y * sc.y + sh.y, 0.f);
    v.z = fmaxf(v.z * sc.z + sh.z, 0.f);
    v.w = fmaxf(v.w * sc.w + sh.w, 0.f);
    ((float4*)t)[i] = v;
}

__global__ void k_pebias(const float* a, const float* b, float* o) {
    int i = threadIdx.x;
    if (i < DIM) o[i] = a[i] + b[i];
}

// ---------------- score (BN+relu+dot fused) ----------------
__global__ void k_score(const float* __restrict__ hpath, const float* __restrict__ scale,
                        const float* __restrict__ shift, const float* __restrict__ sw,
                        float* __restrict__ scores) {
    int gt = blockIdx.x * blockDim.x + threadIdx.x;
    int e = gt >> 5, lane = gt & 31;
    if (e >= NEDGE) return;
    float4 h = ((const float4*)(hpath + (size_t)e * DIM))[lane];
    float4 sc = __ldg(&((const float4*)scale)[lane]);
    float4 sh = __ldg(&((const float4*)shift)[lane]);
    float4 w  = __ldg(&((const float4*)sw)[lane]);
    float s = fmaxf(h.x * sc.x + sh.x, 0.f) * w.x
            + fmaxf(h.y * sc.y + sh.y, 0.f) * w.y
            + fmaxf(h.z * sc.z + sh.z, 0.f) * w.z
            + fmaxf(h.w * sc.w + sh.w, 0.f) * w.w;
    #pragma unroll
    for (int o = 16; o > 0; o >>= 1) s += __shfl_xor_sync(~0u, s, o);
    if (lane == 0) scores[e] = s;
}

// ---------------- top-k (value desc, index asc) ----------------
__device__ __forceinline__ bool kbetter(float a, int ia, float b, int ib) {
    return (a > b) || (a == b && ia < ib);
}

__device__ __forceinline__ void kmerge(const float* av, const int* ai,
                                       const float* bv, const int* bi,
                                       float* ov, int* oi) {
    int x = 0, y = 0;
    for (int k = 0; k < TOPN; k++) {
        if (kbetter(av[x], ai[x], bv[y], bi[y])) { ov[k] = av[x]; oi[k] = ai[x]; x++; }
        else                                      { ov[k] = bv[y]; oi[k] = bi[y]; y++; }
    }
}

__device__ __forceinline__ void block_topk_reduce(float* v, int* id, float* sv, int* si,
                                                  int t) {
    for (int k = 0; k < TOPN; k++) { sv[t * TOPN + k] = v[k]; si[t * TOPN + k] = id[k]; }
    __syncthreads();
    for (int strd = 128; strd > 0; strd >>= 1) {
        if (t < strd) {
            float av[TOPN], bv[TOPN], ov[TOPN];
            int ai[TOPN], bi[TOPN], oi[TOPN];
            for (int k = 0; k < TOPN; k++) {
                av[k] = sv[t * TOPN + k];            ai[k] = si[t * TOPN + k];
                bv[k] = sv[(t + strd) * TOPN + k];   bi[k] = si[(t + strd) * TOPN + k];
            }
            kmerge(av, ai, bv, bi, ov, oi);
            for (int k = 0; k < TOPN; k++) { sv[t * TOPN + k] = ov[k]; si[t * TOPN + k] = oi[k]; }
        }
        __syncthreads();
    }
}

__global__ void k_top1(const float* __restrict__ scores, float* cv, int* ci) {
    __shared__ float sv[256 * TOPN];
    __shared__ int   si[256 * TOPN];
    const float NEG = __int_as_float(0xff800000);
    float v[TOPN]; int id[TOPN];
    for (int k = 0; k < TOPN; k++) { v[k] = NEG; id[k] = 0x7fffffff; }
    int stride = gridDim.x * blockDim.x;
    for (int i = blockIdx.x * blockDim.x + threadIdx.x; i < NEDGE; i += stride) {
        float s = scores[i];
        if (kbetter(s, i, v[TOPN - 1], id[TOPN - 1])) {
            int p = TOPN - 1;
            while (p > 0 && kbetter(s, i, v[p - 1], id[p - 1])) {
                v[p] = v[p - 1]; id[p] = id[p - 1]; p--;
            }
            v[p] = s; id[p] = i;
        }
    }
    block_topk_reduce(v, id, sv, si, threadIdx.x);
    if (threadIdx.x == 0)
        for (int k = 0; k < TOPN; k++) {
            cv[blockIdx.x * TOPN + k] = sv[k];
            ci[blockIdx.x * TOPN + k] = si[k];
        }
}

__global__ void k_top2(const float* __restrict__ cv, const int* __restrict__ ci, float* out) {
    __shared__ float sv[256 * TOPN];
    __shared__ int   si[256 * TOPN];
    int t = threadIdx.x;
    float v[TOPN]; int id[TOPN];
    for (int k = 0; k < TOPN; k++) { v[k] = cv[t * TOPN + k]; id[k] = ci[t * TOPN + k]; }
    block_topk_reduce(v, id, sv, si, t);
    if (t == 0)
        for (int k = 0; k < TOPN; k++) {
            out[k]        = sv[k];
            out[TOPN + k] = (float)si[k];
        }
}

// ---------------- launch ----------------
extern "C" void kernel_launch(void* const* d_in, const int* in_sizes, int n_in,
                              void* d_out, int out_size) {
    const float* F[20];
    for (int i = 0; i < 20 && i < n_in; i++) F[i] = (const float*)d_in[i];

    const float *paths_srcs, *path_feats, *conv_edge_W, *conv_edge_b, *conv_W1,
                *conv_bn_g, *conv_bn_b, *conv_W2, *lin1_W, *lin1_b, *lin2_W, *lin2_b,
                *pe_src_W, *pe_src_b, *pe_tgt_W, *pe_tgt_b, *pe_bn_g, *pe_bn_b, *score_w;
    const int* src_ids;

    if (in_sizes[2] == NEDGE) {
        paths_srcs = F[0]; path_feats = F[1]; src_ids = (const int*)d_in[2];
        conv_edge_W = F[3]; conv_edge_b = F[4]; conv_W1 = F[5];
        conv_bn_g = F[6]; conv_bn_b = F[7]; conv_W2 = F[8];
        lin1_W = F[9]; lin1_b = F[10]; lin2_W = F[11]; lin2_b = F[12];
        pe_src_W = F[13]; pe_src_b = F[14]; pe_tgt_W = F[15]; pe_tgt_b = F[16];
        pe_bn_g = F[17]; pe_bn_b = F[18]; score_w = F[19];
    } else {
        paths_srcs = F[0]; path_feats = F[1];
        conv_edge_W = F[2]; conv_edge_b = F[3]; conv_W1 = F[4];
        conv_bn_g = F[5]; conv_bn_b = F[6]; conv_W2 = F[7];
        lin1_W = F[8]; lin1_b = F[9]; lin2_W = F[10]; lin2_b = F[11];
        pe_src_W = F[12]; pe_src_b = F[13]; pe_tgt_W = F[14]; pe_tgt_b = F[15];
        pe_bn_g = F[16]; pe_bn_b = F[17]; score_w = F[18];
        src_ids = (const int*)d_in[19];
    }

    auto sym = [](const void* s) { void* p = nullptr; cudaGetSymbolAddress(&p, s); return p; };
    float* agg      = (float*)sym(d_agg);
    float* h        = (float*)sym(d_h);
    float* t        = (float*)sym(d_t);
    float* hcat     = (float*)sym(d_hcat);
    float* tmp      = (float*)sym(d_tmp);
    float* nodeproj = (float*)sym(d_nodeproj);
    float* hpath    = (float*)sym(d_hpath);
    float* scores   = (float*)sym(d_scores);
    float* stats    = (float*)sym(d_stats);
    float* bns      = (float*)sym(d_bns);
    float* bnsh     = (float*)sym(d_bnsh);
    float* pebias   = (float*)sym(d_pebias);
    int*   cnt      = (int*)sym(d_cnt);
    int*   off      = (int*)sym(d_off);
    int*   cursor   = (int*)sym(d_cursor);
    int*   elist    = (int*)sym(d_elist);
    float* cv       = (float*)sym(d_cv);
    int*   ci       = (int*)sym(d_ci);
    unsigned short* bhi = (unsigned short*)sym(d_bhi);
    unsigned short* blo = (unsigned short*)sym(d_blo);
    float* out      = (float*)d_out;

    const dim3 blk(256);
    const int NODE_BLKS = (NSRC + 127) / 128;

    cudaFuncSetAttribute(k_pathgemm, cudaFuncAttributeMaxDynamicSharedMemorySize, SMEM_PG);

    // 0) W split (independent; overlaps CSR build)
    k_wconv<<<(128 * 240 + 255) / 256, blk>>>(pe_tgt_W, bhi, blo);

    // 1) CSR build + segment sum of relu(path_feats)
    k_zero<<<(NSRC + 255) / 256, blk>>>(cnt, stats);
    k_hist<<<(NEDGE + 255) / 256, blk>>>(src_ids, cnt);
    k_scan<<<1, 1024>>>(cnt, off, cursor);
    k_scatter<<<(NEDGE + 255) / 256, blk>>>(src_ids, cursor, elist);
    k_agg<<<NSRC, blk>>>(path_feats, elist, off, agg);

    // 2) h_i = agg @ We_i + be_i + paths_srcs
    k_gemm<236, true, false, 1, false><<<dim3(NODE_BLKS, 1, 3), blk>>>(
        agg, 0, conv_edge_W, 236 * 128, conv_edge_b, 128,
        paths_srcs, nullptr, h, NSRC * DIM, DIM, nullptr, 0, NSRC);

    // 3) t_i = h_i @ W1_i with fused BN stats
    k_gemm<128, false, false, 0, true><<<dim3(NODE_BLKS, 1, 3), blk>>>(
        h, NSRC * DIM, conv_W1, DIM * DIM, nullptr, 0,
        nullptr, nullptr, t, NSRC * DIM, DIM, stats, 256, NSRC);

    // 4) BN finalize + apply in place
    k_bnfin<<<2, blk>>>(stats, conv_bn_g, conv_bn_b, 1.f / NSRC, bns, bnsh, 3);
    k_bnrelu<<<(3 * NSRC * 32 + 255) / 256, blk>>>(t, bns, bnsh);

    // 5) hs_i = z_i @ W2_i -> hcat
    k_gemm<128, false, false, 0, false><<<dim3(NODE_BLKS, 1, 3), blk>>>(
        t, NSRC * DIM, conv_W2, DIM * DIM, nullptr, 0,
        nullptr, nullptr, hcat, 128, 3 * DIM, nullptr, 0, NSRC);

    // 6) lin1 (relu) and lin2 -> node_emb into d_out
    k_gemm<384, true, true, 0, false><<<dim3(NODE_BLKS, 1, 1), blk>>>(
        hcat, 0, lin1_W, 0, lin1_b, 0, nullptr, nullptr, tmp, 0, DIM, nullptr, 0, NSRC);
    k_gemm<128, true, false, 0, false><<<dim3(NODE_BLKS, 1, 1), blk>>>(
        tmp, 0, lin2_W, 0, lin2_b, 0, nullptr, nullptr, out, 0, DIM, nullptr, 0, NSRC);

    // 7) node_proj = node_emb @ pe_src_W + (pe_src_b + pe_tgt_b)
    k_pebias<<<1, 128>>>(pe_src_b, pe_tgt_b, pebias);
    k_gemm<128, true, false, 0, false><<<dim3(NODE_BLKS, 1, 1), blk>>>(
        out, 0, pe_src_W, 0, pebias, 0, nullptr, nullptr, nodeproj, 0, DIM, nullptr, 0, NSRC);

    // 8) hpath = path_feats @ pe_tgt_W + node_proj[src]  (mma.sync split-bf16, persistent)
    k_pathgemm<<<148, blk, SMEM_PG>>>(path_feats, bhi, blo, nodeproj, src_ids, hpath);

    // 9) column stats, BN finalize, fused BN+relu+dot(score_w)
    k_colstats<<<296, blk>>>(hpath, stats + 768);
    k_bnfin<<<1, 128>>>(stats + 768, pe_bn_g, pe_bn_b, 1.f / NEDGE, bns + 384, bnsh + 384, 1);
    k_score<<<(NEDGE * 32 + 255) / 256, blk>>>(hpath, bns + 384, bnsh + 384, score_w, scores);

    // 10) top-6
    k_top1<<<256, blk>>>(scores, cv, ci);
    k_top2<<<1, blk>>>(cv, ci, out + (size_t)NSRC * DIM);
}